// round 17
// baseline (speedup 1.0000x reference)
#include <cuda_runtime.h>
#include <math.h>
#include <stdint.h>

#define BATCH 8
#define QN 2048
#define KN 2048
#define DIN 1024
#define DPROJ 1024

// ---------------------------------------------------------------------------
// Scratch (__device__ globals; allocation-free).
// All GEMM operands live here PRE-ROUNDED to tf32 (rna) so that mma.sync's
// tf32 truncation is exact.
// ---------------------------------------------------------------------------
__device__ float g_rq [(size_t)BATCH * QN * DIN];
__device__ float g_rk [(size_t)BATCH * KN * DIN];
__device__ float g_rv [(size_t)BATCH * KN * DIN];
__device__ float g_rwq[(size_t)DPROJ * DIN];
__device__ float g_rwk[(size_t)DPROJ * DIN];
__device__ float g_rwv[(size_t)DPROJ * DIN];
__device__ float g_pq [(size_t)BATCH * QN * DPROJ];
__device__ float g_pk [(size_t)BATCH * KN * DPROJ];
__device__ float g_pvT[(size_t)BATCH * DPROJ * KN];

// ---------------------------------------------------------------------------
__device__ __forceinline__ uint32_t f2tf32(float f) {
    uint32_t u;
    asm("cvt.rna.tf32.f32 %0, %1;" : "=r"(u) : "f"(f));
    return u;
}

__device__ __forceinline__ void mma_tf32(float* d, const uint32_t* a, const uint32_t* b) {
    asm volatile(
        "mma.sync.aligned.m16n8k8.row.col.f32.tf32.tf32.f32 "
        "{%0,%1,%2,%3}, {%4,%5,%6,%7}, {%8,%9}, {%0,%1,%2,%3};\n"
        : "+f"(d[0]), "+f"(d[1]), "+f"(d[2]), "+f"(d[3])
        : "r"(a[0]), "r"(a[1]), "r"(a[2]), "r"(a[3]),
          "r"(b[0]), "r"(b[1]));
}

__device__ __forceinline__ void ldsm4(uint32_t& r0, uint32_t& r1,
                                      uint32_t& r2, uint32_t& r3, uint32_t addr) {
    asm volatile("ldmatrix.sync.aligned.m8n8.x4.shared.b16 {%0,%1,%2,%3}, [%4];"
        : "=r"(r0), "=r"(r1), "=r"(r2), "=r"(r3) : "r"(addr));
}

__device__ __forceinline__ void cp16(uint32_t dst, const void* src) {
    asm volatile("cp.async.cg.shared.global [%0], [%1], 16;" :: "r"(dst), "l"(src) : "memory");
}

// ---------------------------------------------------------------------------
// NT tensor-core GEMM, tf32(pre-rounded)/fp32-acc:
//   C[m,n] = scale*sum_k A[m,k]*Bm[n,k] (+bias)
// BIAS: 0 none, 1 col bias[n], 2 row bias[m].  ROUND: rna-tf32 the output.
// Block 256x128 (8 warps, 4x2, 64x64 warp tile), BK=32, SW128-swizzled smem
// (128B rows, quad = (k>>2)^(r&7)) -> conflict-free cp.async AND ldmatrix.
// 3-stage cp.async pipeline, one __syncthreads per k32. 144KB smem, 1 CTA/SM.
// ---------------------------------------------------------------------------
#define BLKM 256
#define BLKN 128
#define BK 32
#define STAGES 3
#define TILE_A_BYTES (BLKM * 128)                 // 32768
#define TILE_B_BYTES (BLKN * 128)                 // 16384
#define STAGE_BYTES (TILE_A_BYTES + TILE_B_BYTES) // 49152
#define GSMEM_BYTES (STAGES * STAGE_BYTES)        // 147456

template <int BIAS, int ROUND>
__global__ __launch_bounds__(256) void gemm_tc(
    const float* __restrict__ A, const float* __restrict__ Bm,
    const float* __restrict__ bias, float* __restrict__ C,
    int N, int K, float scale,
    long aStride, long bStride, long cStride)
{
    extern __shared__ uint32_t smem[];
    const uint32_t sbase = (uint32_t)__cvta_generic_to_shared(smem);

    const int bm = blockIdx.y * BLKM;
    const int bn = blockIdx.x * BLKN;
    A  += blockIdx.z * aStride;
    Bm += blockIdx.z * bStride;
    C  += blockIdx.z * cStride;

    const int tid  = threadIdx.x;
    const int lane = tid & 31;
    const int wid  = tid >> 5;
    const int wm   = (wid & 3) * 64;   // 4 m-warps
    const int wn   = (wid >> 2) * 64;  // 2 n-warps
    const int lr   = lane >> 2;
    const int lc   = lane & 3;

    // ldmatrix lane geometry (validated): (row & 7) == rl for all frags here.
    const int mi  = lane >> 3;
    const int rl  = lane & 7;
    const int miL = mi & 1;
    const int miH = mi >> 1;
    const uint32_t rowAb = (uint32_t)(wm + rl + miL * 8) * 128;
    const uint32_t rowBb = (uint32_t)(wn + rl + miH * 8) * 128;

    // cp.async geometry: group = tid>>3 (0..31), c = tid&7; row = i*32+group.
    const int cp_g = tid >> 3;
    const int cp_c = tid & 7;

    float acc[4][8][4];
#pragma unroll
    for (int i = 0; i < 4; i++)
#pragma unroll
        for (int j = 0; j < 8; j++)
#pragma unroll
            for (int q = 0; q < 4; q++) acc[i][j][q] = 0.f;

    const int T = K / BK;

    auto cp_tile = [&](int t, int s) {
        const uint32_t sA = sbase + s * STAGE_BYTES;
        const uint32_t sB = sA + TILE_A_BYTES;
        const long k0 = (long)t * BK + cp_c * 4;
#pragma unroll
        for (int i = 0; i < 8; i++) {          // A: 256 rows
            const int row = i * 32 + cp_g;
            const uint32_t soff = (uint32_t)row * 128 +
                                  (uint32_t)((cp_c ^ (row & 7)) << 4);
            cp16(sA + soff, A + (long)(bm + row) * K + k0);
        }
#pragma unroll
        for (int i = 0; i < 4; i++) {          // B: 128 rows
            const int row = i * 32 + cp_g;
            const uint32_t soff = (uint32_t)row * 128 +
                                  (uint32_t)((cp_c ^ (row & 7)) << 4);
            cp16(sB + soff, Bm + (long)(bn + row) * K + k0);
        }
        asm volatile("cp.async.commit_group;" ::: "memory");
    };

    auto compute = [&](int s) {
        const uint32_t sA = sbase + s * STAGE_BYTES + rowAb;
        const uint32_t sB = sbase + s * STAGE_BYTES + TILE_A_BYTES + rowBb;
#pragma unroll
        for (int k8 = 0; k8 < 4; k8++) {
            uint32_t af[4][4], bf[8][2];
            const uint32_t qa = (uint32_t)(((k8 * 2 + miH) ^ rl) << 4);
            const uint32_t qb = (uint32_t)(((k8 * 2 + miL) ^ rl) << 4);
#pragma unroll
            for (int fm = 0; fm < 4; fm++)
                ldsm4(af[fm][0], af[fm][1], af[fm][2], af[fm][3],
                      sA + fm * 2048 + qa);
#pragma unroll
            for (int fp = 0; fp < 4; fp++)
                ldsm4(bf[2 * fp][0], bf[2 * fp][1], bf[2 * fp + 1][0], bf[2 * fp + 1][1],
                      sB + fp * 2048 + qb);
#pragma unroll
            for (int fm = 0; fm < 4; fm++)
#pragma unroll
                for (int fn = 0; fn < 8; fn++)
                    mma_tf32(acc[fm][fn], af[fm], bf[fn]);
        }
    };

    // Prologue: stages 0,1
    cp_tile(0, 0);
    cp_tile(1, 1);

    int s = 0;
    for (int t = 0; t < T; t++) {
        if (t + 1 < T) asm volatile("cp.async.wait_group 1;" ::: "memory");
        else           asm volatile("cp.async.wait_group 0;" ::: "memory");
        __syncthreads();   // tile t visible; stage (t+2)%3 fully consumed
        if (t + 2 < T) {
            int sn = s + 2; if (sn >= STAGES) sn -= STAGES;
            cp_tile(t + 2, sn);
        }
        compute(s);
        if (++s == STAGES) s = 0;
    }

    // Epilogue (fragment layout validated rounds 7-9)
#pragma unroll
    for (int fm = 0; fm < 4; fm++) {
        const int r = bm + wm + fm * 16 + lr;
        float br0 = 0.f, br1 = 0.f;
        if (BIAS == 2) { br0 = bias[r]; br1 = bias[r + 8]; }
#pragma unroll
        for (int fn = 0; fn < 8; fn++) {
            const int c = bn + wn + fn * 8 + lc * 2;
            float bc0 = 0.f, bc1 = 0.f;
            if (BIAS == 1) { bc0 = bias[c]; bc1 = bias[c + 1]; }
            float2 v0, v1;
            v0.x = acc[fm][fn][0] * scale + bc0 + br0;
            v0.y = acc[fm][fn][1] * scale + bc1 + br0;
            v1.x = acc[fm][fn][2] * scale + bc0 + br1;
            v1.y = acc[fm][fn][3] * scale + bc1 + br1;
            if (ROUND) {
                v0.x = __uint_as_float(f2tf32(v0.x));
                v0.y = __uint_as_float(f2tf32(v0.y));
                v1.x = __uint_as_float(f2tf32(v1.x));
                v1.y = __uint_as_float(f2tf32(v1.y));
            }
            *(float2*)&C[(long)r * N + c] = v0;
            *(float2*)&C[(long)(r + 8) * N + c] = v1;
        }
    }
}

// ---------------------------------------------------------------------------
// Elementwise fp32 -> tf32(rna) pre-round
// ---------------------------------------------------------------------------
__global__ __launch_bounds__(256) void round_tf32_k(
    const float4* __restrict__ in, float4* __restrict__ out, long n4)
{
    long i = (long)blockIdx.x * blockDim.x + threadIdx.x;
    const long st = (long)gridDim.x * blockDim.x;
    for (; i < n4; i += st) {
        float4 v = in[i];
        float4 o;
        o.x = __uint_as_float(f2tf32(v.x));
        o.y = __uint_as_float(f2tf32(v.y));
        o.z = __uint_as_float(f2tf32(v.z));
        o.w = __uint_as_float(f2tf32(v.w));
        out[i] = o;
    }
}

// ---------------------------------------------------------------------------
// Row softmax with mask; output tf32-rounded (feeds ctx GEMM).
// Masked entries contribute nothing and output exact 0 (matches reference).
// ---------------------------------------------------------------------------
__global__ __launch_bounds__(256) void softmax_mask(
    float* __restrict__ S, const int* __restrict__ mask)
{
    const int row = blockIdx.x;
    const int b = row / QN;
    float* sp = S + (long)row * KN;
    const int* mp = mask + (long)b * KN;

    const int tid = threadIdx.x;
    __shared__ float red[32];

    float vals[8];
    int ms[8];
    float lmax = -INFINITY;
#pragma unroll
    for (int i = 0; i < 8; i++) {
        int k = tid + i * 256;
        vals[i] = sp[k];
        ms[i] = mp[k];
        if (ms[i]) lmax = fmaxf(lmax, vals[i]);
    }
#pragma unroll
    for (int o = 16; o > 0; o >>= 1)
        lmax = fmaxf(lmax, __shfl_xor_sync(0xffffffffu, lmax, o));
    if ((tid & 31) == 0) red[tid >> 5] = lmax;
    __syncthreads();
    float rmax = (tid < 8) ? red[tid] : -INFINITY;
#pragma unroll
    for (int o = 4; o > 0; o >>= 1)
        rmax = fmaxf(rmax, __shfl_xor_sync(0xffffffffu, rmax, o));
    if (tid == 0) red[0] = rmax;
    __syncthreads();
    rmax = red[0];

    float lsum = 0.f;
#pragma unroll
    for (int i = 0; i < 8; i++) {
        vals[i] = ms[i] ? __expf(vals[i] - rmax) : 0.f;
        lsum += vals[i];
    }
#pragma unroll
    for (int o = 16; o > 0; o >>= 1)
        lsum += __shfl_xor_sync(0xffffffffu, lsum, o);
    __syncthreads();
    if ((tid & 31) == 0) red[tid >> 5] = lsum;
    __syncthreads();
    float rsum = (tid < 8) ? red[tid] : 0.f;
#pragma unroll
    for (int o = 4; o > 0; o >>= 1)
        rsum += __shfl_xor_sync(0xffffffffu, rsum, o);
    if (tid == 0) red[0] = rsum;
    __syncthreads();
    rsum = red[0];

    float inv = (rsum > 0.f) ? (1.f / rsum) : 0.f;
#pragma unroll
    for (int i = 0; i < 8; i++) {
        int k = tid + i * 256;
        sp[k] = __uint_as_float(f2tf32(vals[i] * inv));
    }
}

// ---------------------------------------------------------------------------
// kernel_launch
// Inputs: query, key, value, mask, Wq, bq, Wk, bk, Wv, bv
// Output: [ctx (B*QN*DPROJ) | attn (B*QN*KN)]
// ---------------------------------------------------------------------------
extern "C" void kernel_launch(void* const* d_in, const int* in_sizes, int n_in,
                              void* d_out, int out_size)
{
    const float* query = (const float*)d_in[0];
    const float* key   = (const float*)d_in[1];
    const float* value = (const float*)d_in[2];
    const int*   mask  = (const int*)d_in[3];
    const float* Wq    = (const float*)d_in[4];
    const float* bq    = (const float*)d_in[5];
    const float* Wk    = (const float*)d_in[6];
    const float* bk    = (const float*)d_in[7];
    const float* Wv    = (const float*)d_in[8];
    const float* bv    = (const float*)d_in[9];

    float* ctx  = (float*)d_out;
    float* attn = (float*)d_out + (size_t)BATCH * QN * DPROJ;

    float *rq, *rk, *rv, *rwq, *rwk, *rwv, *pq, *pk, *pvT;
    cudaGetSymbolAddress((void**)&rq,  g_rq);
    cudaGetSymbolAddress((void**)&rk,  g_rk);
    cudaGetSymbolAddress((void**)&rv,  g_rv);
    cudaGetSymbolAddress((void**)&rwq, g_rwq);
    cudaGetSymbolAddress((void**)&rwk, g_rwk);
    cudaGetSymbolAddress((void**)&rwv, g_rwv);
    cudaGetSymbolAddress((void**)&pq,  g_pq);
    cudaGetSymbolAddress((void**)&pk,  g_pk);
    cudaGetSymbolAddress((void**)&pvT, g_pvT);

    cudaFuncSetAttribute(gemm_tc<0, 0>, cudaFuncAttributeMaxDynamicSharedMemorySize, GSMEM_BYTES);
    cudaFuncSetAttribute(gemm_tc<1, 1>, cudaFuncAttributeMaxDynamicSharedMemorySize, GSMEM_BYTES);
    cudaFuncSetAttribute(gemm_tc<2, 1>, cudaFuncAttributeMaxDynamicSharedMemorySize, GSMEM_BYTES);

    // 1) Pre-round all external GEMM inputs to tf32 (rna) once.
    {
        const long nBig = (long)BATCH * QN * DIN / 4;
        const long nW   = (long)DPROJ * DIN / 4;
        round_tf32_k<<<2048, 256>>>((const float4*)query, (float4*)rq, nBig);
        round_tf32_k<<<2048, 256>>>((const float4*)key,   (float4*)rk, nBig);
        round_tf32_k<<<2048, 256>>>((const float4*)value, (float4*)rv, nBig);
        round_tf32_k<<<512, 256>>>((const float4*)Wq, (float4*)rwq, nW);
        round_tf32_k<<<512, 256>>>((const float4*)Wk, (float4*)rwk, nW);
        round_tf32_k<<<512, 256>>>((const float4*)Wv, (float4*)rwv, nW);
    }

    dim3 blk(256);

    // 2) Q/K projections (batches fused): pq[tok,d] = rq @ rwq^T + bq (col-bias, rounded)
    {
        dim3 grid(DPROJ / BLKN, (BATCH * QN) / BLKM, 1);
        gemm_tc<1, 1><<<grid, blk, GSMEM_BYTES>>>(rq, rwq, bq, pq, DPROJ, DIN, 1.f, 0, 0, 0);
        gemm_tc<1, 1><<<grid, blk, GSMEM_BYTES>>>(rk, rwk, bk, pk, DPROJ, DIN, 1.f, 0, 0, 0);
    }

    // 3) V projection transposed: pvT[d,tok] = rwv @ rv^T + bv[d] (row-bias, rounded)
    {
        dim3 grid(KN / BLKN, DPROJ / BLKM, BATCH);
        gemm_tc<2, 1><<<grid, blk, GSMEM_BYTES>>>(rwv, rv, bv, pvT, KN, DIN, 1.f,
                                                  0, (long)KN * DIN, (long)DPROJ * KN);
    }

    // 4) Scores: attn_raw[q,k] = (pq . pk)/32 per batch (unrounded fp32 out)
    {
        dim3 grid(KN / BLKN, QN / BLKM, BATCH);
        gemm_tc<0, 0><<<grid, blk, GSMEM_BYTES>>>(pq, pk, nullptr, attn, KN, DPROJ,
                                                  0.03125f,
                                                  (long)QN * DPROJ, (long)KN * DPROJ,
                                                  (long)QN * KN);
    }

    // 5) Masked softmax in-place (output tf32-rounded)
    softmax_mask<<<BATCH * QN, 256>>>(attn, mask);

    // 6) ctx[q,d] = sum_k attn[q,k] * pvT[d,k]  (NT)
    {
        dim3 grid(DPROJ / BLKN, QN / BLKM, BATCH);
        gemm_tc<0, 0><<<grid, blk, GSMEM_BYTES>>>(attn, pvT, nullptr, ctx, DPROJ, KN,
                                                  1.f,
                                                  (long)QN * KN, (long)DPROJ * KN,
                                                  (long)QN * DPROJ);
    }
}